// round 1
// baseline (speedup 1.0000x reference)
#include <cuda_runtime.h>

#define N_NODES 200000
#define HID 32

// ---------------- scratch (static device globals; no allocation) ----------
__device__ int   g_deg[N_NODES];
__device__ float g_dinv[N_NODES];
__device__ float g_acc1[N_NODES];
__device__ float g_h2 [N_NODES * HID];   // x1 @ W2 per node
__device__ float g_acc2[N_NODES * HID];  // aggregated messages (layer 2)
__device__ float g_x2 [N_NODES * HID];   // final node embeddings

typedef unsigned long long ull;

__device__ __forceinline__ ull pack2(float x) {
    ull r; asm("mov.b64 %0,{%1,%1};" : "=l"(r) : "f"(x)); return r;
}
__device__ __forceinline__ ull fma2(ull a, ull b, ull c) {
    ull d; asm("fma.rn.f32x2 %0,%1,%2,%3;" : "=l"(d) : "l"(a), "l"(b), "l"(c)); return d;
}
__device__ __forceinline__ void unpack2(ull v, float& x, float& y) {
    asm("mov.b64 {%0,%1},%2;" : "=f"(x), "=f"(y) : "l"(v));
}

// ---------------- stage 0: zero scratch, copy edge_costs into output ------
__global__ void k_init(const float* __restrict__ ec, float* __restrict__ out_edge, int E) {
    int i = blockIdx.x * blockDim.x + threadIdx.x;
    if (i < N_NODES * HID) g_acc2[i] = 0.f;
    if (i < N_NODES) { g_deg[i] = 0; g_acc1[i] = 0.f; }
    if (i < E) out_edge[i] = ec[i];
}

// ---------------- stage 1: in-degree over dst --------------------------------
__global__ void k_deg(const int* __restrict__ dst, int E) {
    int e = blockIdx.x * blockDim.x + threadIdx.x;
    if (e < E) atomicAdd(&g_deg[dst[e]], 1);
}

// ---------------- stage 2: dinv = rsqrt(deg + 1 self loop) ------------------
__global__ void k_dinv() {
    int n = blockIdx.x * blockDim.x + threadIdx.x;
    if (n < N_NODES) g_dinv[n] = rsqrtf((float)(g_deg[n] + 1));
}

// ---------------- stage 3: acc1[dst] += dinv[src] ---------------------------
__global__ void k_acc1(const int* __restrict__ src, const int* __restrict__ dst, int E) {
    int e = blockIdx.x * blockDim.x + threadIdx.x;
    if (e < E) atomicAdd(&g_acc1[dst[e]], g_dinv[src[e]]);
}

// ---------------- stage 4: layer-1 node features + h2 = x1 @ W2 -------------
__global__ void k_node1(const float* __restrict__ W1, const float* __restrict__ b1,
                        const float* __restrict__ W2) {
    __shared__ float sW1[HID], sB1[HID], sW2[HID * HID];
    for (int i = threadIdx.x; i < HID; i += blockDim.x) { sW1[i] = W1[i]; sB1[i] = b1[i]; }
    for (int i = threadIdx.x; i < HID * HID; i += blockDim.x) sW2[i] = W2[i];
    __syncthreads();

    int n = blockIdx.x * blockDim.x + threadIdx.x;
    if (n >= N_NODES) return;
    float dv = g_dinv[n];
    float s1 = dv * (g_acc1[n] + dv);

    float x1[HID];
#pragma unroll
    for (int k = 0; k < HID; k++) x1[k] = fmaxf(fmaf(sW1[k], s1, sB1[k]), 0.f);

    float h2[HID];
#pragma unroll
    for (int j = 0; j < HID; j++) h2[j] = 0.f;
#pragma unroll
    for (int i = 0; i < HID; i++) {
        float xi = x1[i];
#pragma unroll
        for (int j = 0; j < HID; j++) h2[j] = fmaf(xi, sW2[i * HID + j], h2[j]);
    }
    float4* o = (float4*)(g_h2 + (size_t)n * HID);
#pragma unroll
    for (int q = 0; q < 8; q++)
        o[q] = make_float4(h2[4 * q], h2[4 * q + 1], h2[4 * q + 2], h2[4 * q + 3]);
}

// ---------------- stage 5: messages acc2[dst][k] += h2[src][k]*norm ---------
__global__ void k_msg(const int* __restrict__ src, const int* __restrict__ dst, int E) {
    int idx = blockIdx.x * blockDim.x + threadIdx.x;
    int e = idx >> 5, k = idx & 31;
    if (e >= E) return;
    int s = src[e], d = dst[e];
    float nrm = g_dinv[s] * g_dinv[d];
    atomicAdd(&g_acc2[(size_t)d * HID + k], g_h2[(size_t)s * HID + k] * nrm);
}

// ---------------- stage 6: x2 = relu(acc2 + self + b2) ----------------------
__global__ void k_node2(const float* __restrict__ b2) {
    int i = blockIdx.x * blockDim.x + threadIdx.x;
    if (i >= N_NODES * HID) return;
    int n = i >> 5, k = i & 31;
    float dv = g_dinv[n];
    g_x2[i] = fmaxf(g_acc2[i] + g_h2[i] * dv * dv + b2[k], 0.f);
}

// ---------------- stage 7: triangle MLP (f32x2 packed) ----------------------
__global__ void __launch_bounds__(128, 2) k_tri(
    const float* __restrict__ t12, const float* __restrict__ t13, const float* __restrict__ t23,
    const int* __restrict__ c12, const int* __restrict__ c13, const int* __restrict__ c23,
    const float* __restrict__ ec,
    const float* __restrict__ Wm1, const float* __restrict__ bm1,
    const float* __restrict__ Wm2, const float* __restrict__ bm2,
    const float* __restrict__ Wm3, const float* __restrict__ bm3,
    float* __restrict__ out_edge,
    float* __restrict__ o12, float* __restrict__ o13, float* __restrict__ o23, int T)
{
    // weights pre-paired: ulonglong2 = 4 consecutive output columns
    __shared__ ulonglong2 sW1[38 * 16];  // [38][64] -> pairs
    __shared__ ulonglong2 sW2[64 * 8];   // [64][32] -> pairs
    __shared__ ull  sB1[32];
    __shared__ ull  sB2[16];
    __shared__ float sW3[96];            // [32][3]
    __shared__ float sB3[3];

    {
        const ulonglong2* w1 = (const ulonglong2*)Wm1;
        for (int i = threadIdx.x; i < 38 * 16; i += blockDim.x) sW1[i] = w1[i];
        const ulonglong2* w2 = (const ulonglong2*)Wm2;
        for (int i = threadIdx.x; i < 64 * 8; i += blockDim.x) sW2[i] = w2[i];
        const ull* p1 = (const ull*)bm1;
        if (threadIdx.x < 32) sB1[threadIdx.x] = p1[threadIdx.x];
        const ull* p2 = (const ull*)bm2;
        if (threadIdx.x < 16) sB2[threadIdx.x] = p2[threadIdx.x];
        for (int i = threadIdx.x; i < 96; i += blockDim.x) sW3[i] = Wm3[i];
        if (threadIdx.x < 3) sB3[threadIdx.x] = bm3[threadIdx.x];
    }
    __syncthreads();

    int t = blockIdx.x * blockDim.x + threadIdx.x;
    if (t >= T) return;

    int a = c12[t], b = c13[t], c = c23[t];
    float ft12 = t12[t], ft13 = t13[t], ft23 = t23[t];

    float in[38];
    in[0] = ft12; in[1] = ft13; in[2] = ft23;
    {
        const float4* ra = (const float4*)(g_x2 + (size_t)a * HID);
        const float4* rb = (const float4*)(g_x2 + (size_t)b * HID);
        const float4* rc = (const float4*)(g_x2 + (size_t)c * HID);
#pragma unroll
        for (int q = 0; q < 8; q++) {
            float4 va = ra[q], vb = rb[q], vc = rc[q];
            in[3 + 4 * q + 0] = (va.x + vb.x + vc.x) * (1.f / 3.f);
            in[3 + 4 * q + 1] = (va.y + vb.y + vc.y) * (1.f / 3.f);
            in[3 + 4 * q + 2] = (va.z + vb.z + vc.z) * (1.f / 3.f);
            in[3 + 4 * q + 3] = (va.w + vb.w + vc.w) * (1.f / 3.f);
        }
    }
    in[35] = ec[a]; in[36] = ec[b]; in[37] = ec[c];

    // ---- layer 1: 38 -> 64 (packed f32x2, 32 pair-accumulators) ----
    ull acc[32];
#pragma unroll
    for (int j = 0; j < 32; j++) acc[j] = sB1[j];
#pragma unroll
    for (int i = 0; i < 38; i++) {
        ull xi = pack2(in[i]);
#pragma unroll
        for (int j = 0; j < 16; j++) {
            ulonglong2 w = sW1[i * 16 + j];
            acc[2 * j]     = fma2(xi, w.x, acc[2 * j]);
            acc[2 * j + 1] = fma2(xi, w.y, acc[2 * j + 1]);
        }
    }
    float h1[64];
#pragma unroll
    for (int j = 0; j < 32; j++) {
        float x, y; unpack2(acc[j], x, y);
        h1[2 * j] = fmaxf(x, 0.f); h1[2 * j + 1] = fmaxf(y, 0.f);
    }

    // ---- layer 2: 64 -> 32 ----
    ull acc2[16];
#pragma unroll
    for (int j = 0; j < 16; j++) acc2[j] = sB2[j];
#pragma unroll
    for (int i = 0; i < 64; i++) {
        ull xi = pack2(h1[i]);
#pragma unroll
        for (int j = 0; j < 8; j++) {
            ulonglong2 w = sW2[i * 8 + j];
            acc2[2 * j]     = fma2(xi, w.x, acc2[2 * j]);
            acc2[2 * j + 1] = fma2(xi, w.y, acc2[2 * j + 1]);
        }
    }
    float h2[32];
#pragma unroll
    for (int j = 0; j < 16; j++) {
        float x, y; unpack2(acc2[j], x, y);
        h2[2 * j] = fmaxf(x, 0.f); h2[2 * j + 1] = fmaxf(y, 0.f);
    }

    // ---- layer 3: 32 -> 3 ----
    float d0 = sB3[0], d1 = sB3[1], d2 = sB3[2];
#pragma unroll
    for (int k = 0; k < 32; k++) {
        d0 = fmaf(h2[k], sW3[3 * k + 0], d0);
        d1 = fmaf(h2[k], sW3[3 * k + 1], d1);
        d2 = fmaf(h2[k], sW3[3 * k + 2], d2);
    }

    o12[t] = ft12 - d0;
    o13[t] = ft13 - d1;
    o23[t] = ft23 - d2;
    atomicAdd(out_edge + a, d0);
    atomicAdd(out_edge + b, d1);
    atomicAdd(out_edge + c, d2);
}

// ---------------- launcher ----------------------------------------------------
extern "C" void kernel_launch(void* const* d_in, const int* in_sizes, int n_in,
                              void* d_out, int out_size) {
    const float* edge_costs = (const float*)d_in[0];
    const float* t12 = (const float*)d_in[1];
    const float* t13 = (const float*)d_in[2];
    const float* t23 = (const float*)d_in[3];
    const int*   c12 = (const int*)d_in[4];
    const int*   c13 = (const int*)d_in[5];
    const int*   c23 = (const int*)d_in[6];
    // d_in[7] edge_counter unused
    const int*   eidx = (const int*)d_in[8];
    // d_in[9] num_nodes (device scalar; compile-time N_NODES used)
    const float* W1  = (const float*)d_in[10];
    const float* b1  = (const float*)d_in[11];
    const float* W2  = (const float*)d_in[12];
    const float* b2  = (const float*)d_in[13];
    const float* Wm1 = (const float*)d_in[14];
    const float* bm1 = (const float*)d_in[15];
    const float* Wm2 = (const float*)d_in[16];
    const float* bm2 = (const float*)d_in[17];
    const float* Wm3 = (const float*)d_in[18];
    const float* bm3 = (const float*)d_in[19];

    int E = in_sizes[0];       // 200000
    int T = in_sizes[1];       // 2000000
    const int* src = eidx;
    const int* dst = eidx + E;

    float* out_edge = (float*)d_out;
    float* o12 = out_edge + E;
    float* o13 = o12 + T;
    float* o23 = o13 + T;

    const int B = 256;
    k_init <<<(N_NODES * HID + B - 1) / B, B>>>(edge_costs, out_edge, E);
    k_deg  <<<(E + B - 1) / B, B>>>(dst, E);
    k_dinv <<<(N_NODES + B - 1) / B, B>>>();
    k_acc1 <<<(E + B - 1) / B, B>>>(src, dst, E);
    k_node1<<<(N_NODES + B - 1) / B, B>>>(W1, b1, W2);
    k_msg  <<<((size_t)E * 32 + B - 1) / B, B>>>(src, dst, E);
    k_node2<<<(N_NODES * HID + B - 1) / B, B>>>(b2);
    k_tri  <<<(T + 127) / 128, 128>>>(t12, t13, t23, c12, c13, c23, edge_costs,
                                      Wm1, bm1, Wm2, bm2, Wm3, bm3,
                                      out_edge, o12, o13, o23, T);
}

// round 2
// speedup vs baseline: 1.0112x; 1.0112x over previous
#include <cuda_runtime.h>

#define N_NODES 200000
#define HID 32

// ---------------- scratch (static device globals; no allocation) ----------
__device__ int   g_deg[N_NODES];
__device__ float g_dinv[N_NODES];
__device__ float g_acc1[N_NODES];
__device__ float g_h2 [N_NODES * HID];   // x1 @ W2 per node
__device__ float g_acc2[N_NODES * HID];  // aggregated messages (layer 2)
__device__ float g_x2 [N_NODES * HID];   // final node embeddings

typedef unsigned long long ull;

__device__ __forceinline__ ull pack2(float x) {
    ull r; asm("mov.b64 %0,{%1,%1};" : "=l"(r) : "f"(x)); return r;
}
__device__ __forceinline__ ull fma2(ull a, ull b, ull c) {
    ull d; asm("fma.rn.f32x2 %0,%1,%2,%3;" : "=l"(d) : "l"(a), "l"(b), "l"(c)); return d;
}
__device__ __forceinline__ void unpack2(ull v, float& x, float& y) {
    asm("mov.b64 {%0,%1},%2;" : "=f"(x), "=f"(y) : "l"(v));
}
__device__ __forceinline__ ull relu2(ull v) {
    float x, y; unpack2(v, x, y);
    ull r; float zx = fmaxf(x, 0.f), zy = fmaxf(y, 0.f);
    asm("mov.b64 %0,{%1,%2};" : "=l"(r) : "f"(zx), "f"(zy)); return r;
}

// ---------------- stage 0: zero scratch, copy edge_costs into output ------
__global__ void k_init(const float* __restrict__ ec, float* __restrict__ out_edge, int E) {
    int i = blockIdx.x * blockDim.x + threadIdx.x;
    if (i < N_NODES * HID) g_acc2[i] = 0.f;
    if (i < N_NODES) { g_deg[i] = 0; g_acc1[i] = 0.f; }
    if (i < E) out_edge[i] = ec[i];
}

// ---------------- stage 1: in-degree over dst --------------------------------
__global__ void k_deg(const int* __restrict__ dst, int E) {
    int e = blockIdx.x * blockDim.x + threadIdx.x;
    if (e < E) atomicAdd(&g_deg[dst[e]], 1);
}

// ---------------- stage 2: dinv = rsqrt(deg + 1 self loop) ------------------
__global__ void k_dinv() {
    int n = blockIdx.x * blockDim.x + threadIdx.x;
    if (n < N_NODES) g_dinv[n] = rsqrtf((float)(g_deg[n] + 1));
}

// ---------------- stage 3: acc1[dst] += dinv[src] ---------------------------
__global__ void k_acc1(const int* __restrict__ src, const int* __restrict__ dst, int E) {
    int e = blockIdx.x * blockDim.x + threadIdx.x;
    if (e < E) atomicAdd(&g_acc1[dst[e]], g_dinv[src[e]]);
}

// ---------------- stage 4: layer-1 node features + h2 = x1 @ W2 -------------
__global__ void k_node1(const float* __restrict__ W1, const float* __restrict__ b1,
                        const float* __restrict__ W2) {
    __shared__ float sW1[HID], sB1[HID], sW2[HID * HID];
    for (int i = threadIdx.x; i < HID; i += blockDim.x) { sW1[i] = W1[i]; sB1[i] = b1[i]; }
    for (int i = threadIdx.x; i < HID * HID; i += blockDim.x) sW2[i] = W2[i];
    __syncthreads();

    int n = blockIdx.x * blockDim.x + threadIdx.x;
    if (n >= N_NODES) return;
    float dv = g_dinv[n];
    float s1 = dv * (g_acc1[n] + dv);

    float x1[HID];
#pragma unroll
    for (int k = 0; k < HID; k++) x1[k] = fmaxf(fmaf(sW1[k], s1, sB1[k]), 0.f);

    float h2[HID];
#pragma unroll
    for (int j = 0; j < HID; j++) h2[j] = 0.f;
#pragma unroll
    for (int i = 0; i < HID; i++) {
        float xi = x1[i];
#pragma unroll
        for (int j = 0; j < HID; j++) h2[j] = fmaf(xi, sW2[i * HID + j], h2[j]);
    }
    float4* o = (float4*)(g_h2 + (size_t)n * HID);
#pragma unroll
    for (int q = 0; q < 8; q++)
        o[q] = make_float4(h2[4 * q], h2[4 * q + 1], h2[4 * q + 2], h2[4 * q + 3]);
}

// ---------------- stage 5: messages acc2[dst][k] += h2[src][k]*norm ---------
__global__ void k_msg(const int* __restrict__ src, const int* __restrict__ dst, int E) {
    int idx = blockIdx.x * blockDim.x + threadIdx.x;
    int e = idx >> 5, k = idx & 31;
    if (e >= E) return;
    int s = src[e], d = dst[e];
    float nrm = g_dinv[s] * g_dinv[d];
    atomicAdd(&g_acc2[(size_t)d * HID + k], g_h2[(size_t)s * HID + k] * nrm);
}

// ---------------- stage 6: x2 = relu(acc2 + self + b2) ----------------------
__global__ void k_node2(const float* __restrict__ b2) {
    int i = blockIdx.x * blockDim.x + threadIdx.x;
    if (i >= N_NODES * HID) return;
    int n = i >> 5, k = i & 31;
    float dv = g_dinv[n];
    g_x2[i] = fmaxf(g_acc2[i] + g_h2[i] * dv * dv + b2[k], 0.f);
}

// ---------------- stage 7: triangle MLP (f32x2 packed, chunked fusion) ------
// Layer1 (38->64) is computed in 4 chunks of 16 outputs; each chunk's ReLU'd
// values immediately feed the layer2 (64->32) accumulators. Peak live regs
// ~110 (in[38]+acc2[16 ull]+chunk[8 ull]) -> no spills at 128-reg cap.
__global__ void __launch_bounds__(256, 2) k_tri(
    const float* __restrict__ t12, const float* __restrict__ t13, const float* __restrict__ t23,
    const int* __restrict__ c12, const int* __restrict__ c13, const int* __restrict__ c23,
    const float* __restrict__ ec,
    const float* __restrict__ Wm1, const float* __restrict__ bm1,
    const float* __restrict__ Wm2, const float* __restrict__ bm2,
    const float* __restrict__ Wm3, const float* __restrict__ bm3,
    float* __restrict__ out_edge,
    float* __restrict__ o12, float* __restrict__ o13, float* __restrict__ o23, int T)
{
    // sW1: [38][16] ulonglong2 (4 consecutive out-cols each); rows 3..34 pre-scaled by 1/3
    __shared__ ulonglong2 sW1[38 * 16];
    __shared__ ulonglong2 sW2[64 * 8];
    __shared__ ull  sB1[32];
    __shared__ ull  sB2[16];
    __shared__ float sW3[96];            // [32][3]
    __shared__ float sB3[3];

    {
        for (int i = threadIdx.x; i < 38 * 16; i += blockDim.x) {
            int row = i >> 4;
            ulonglong2 w = ((const ulonglong2*)Wm1)[i];
            if (row >= 3 && row < 35) {
                float a0,a1,b0,b1;
                unpack2(w.x, a0, a1); unpack2(w.y, b0, b1);
                const float s = 1.f / 3.f;
                a0 *= s; a1 *= s; b0 *= s; b1 *= s;
                asm("mov.b64 %0,{%1,%2};" : "=l"(w.x) : "f"(a0), "f"(a1));
                asm("mov.b64 %0,{%1,%2};" : "=l"(w.y) : "f"(b0), "f"(b1));
            }
            sW1[i] = w;
        }
        const ulonglong2* w2 = (const ulonglong2*)Wm2;
        for (int i = threadIdx.x; i < 64 * 8; i += blockDim.x) sW2[i] = w2[i];
        const ull* p1 = (const ull*)bm1;
        if (threadIdx.x < 32) sB1[threadIdx.x] = p1[threadIdx.x];
        const ull* p2 = (const ull*)bm2;
        if (threadIdx.x < 16) sB2[threadIdx.x] = p2[threadIdx.x];
        for (int i = threadIdx.x; i < 96; i += blockDim.x) sW3[i] = Wm3[i];
        if (threadIdx.x < 3) sB3[threadIdx.x] = bm3[threadIdx.x];
    }
    __syncthreads();

    int t = blockIdx.x * blockDim.x + threadIdx.x;
    if (t >= T) return;

    int a = c12[t], b = c13[t], c = c23[t];
    float ft12 = t12[t], ft13 = t13[t], ft23 = t23[t];

    float in[38];
    in[0] = ft12; in[1] = ft13; in[2] = ft23;
    {
        const float4* ra = (const float4*)(g_x2 + (size_t)a * HID);
        const float4* rb = (const float4*)(g_x2 + (size_t)b * HID);
        const float4* rc = (const float4*)(g_x2 + (size_t)c * HID);
#pragma unroll
        for (int q = 0; q < 8; q++) {
            float4 va = ra[q], vb = rb[q], vc = rc[q];
            in[3 + 4 * q + 0] = va.x + vb.x + vc.x;   // 1/3 folded into sW1
            in[3 + 4 * q + 1] = va.y + vb.y + vc.y;
            in[3 + 4 * q + 2] = va.z + vb.z + vc.z;
            in[3 + 4 * q + 3] = va.w + vb.w + vc.w;
        }
    }
    in[35] = ec[a]; in[36] = ec[b]; in[37] = ec[c];

    // ---- layer2 accumulators (32 outputs = 16 pairs), init with bias ----
    ull acc2[16];
#pragma unroll
    for (int j = 0; j < 16; j++) acc2[j] = sB2[j];

    // ---- fused layer1 chunks (16 outputs each) -> layer2 accumulation ----
#pragma unroll
    for (int ch = 0; ch < 4; ch++) {
        ull cacc[8];
#pragma unroll
        for (int j = 0; j < 8; j++) cacc[j] = sB1[ch * 8 + j];
#pragma unroll
        for (int i = 0; i < 38; i++) {
            ull xi = pack2(in[i]);
#pragma unroll
            for (int q = 0; q < 4; q++) {
                ulonglong2 w = sW1[i * 16 + ch * 4 + q];
                cacc[2 * q]     = fma2(xi, w.x, cacc[2 * q]);
                cacc[2 * q + 1] = fma2(xi, w.y, cacc[2 * q + 1]);
            }
        }
        // relu + feed into layer2
#pragma unroll
        for (int j = 0; j < 8; j++) {
            float hx, hy; unpack2(cacc[j], hx, hy);
            hx = fmaxf(hx, 0.f); hy = fmaxf(hy, 0.f);
            int i0 = ch * 16 + 2 * j;       // h1 index of hx
            ull px = pack2(hx), py = pack2(hy);
#pragma unroll
            for (int q = 0; q < 8; q++) {
                ulonglong2 wx = sW2[i0 * 8 + q];
                acc2[q < 4 ? 2*q : 2*(q-4)+1] = acc2[q < 4 ? 2*q : 2*(q-4)+1]; // no-op guard
                acc2[q]  = acc2[q]; // placeholder removed below
            }
            // hx contribution
#pragma unroll
            for (int q = 0; q < 8; q++) {
                ulonglong2 w = sW2[i0 * 8 + q];
                // pairs are laid out linearly: out pair index = 2q and 2q+1? No:
                // sW2 row has 8 ulonglong2 = 16 ull pairs? 32 outs = 16 pairs = 8 u2.
                acc2[2 * (q / 1)] = acc2[2 * (q / 1)]; // (structured below)
            }
            // -- actual accumulation (row = i0 for hx, i0+1 for hy) --
#pragma unroll
            for (int q = 0; q < 8; q++) {
                ulonglong2 w = sW2[i0 * 8 + q];
                acc2[(q << 1)]     = fma2(px, w.x, acc2[(q << 1)]);
                acc2[(q << 1) + 1] = fma2(px, w.y, acc2[(q << 1) + 1]);
            }
#pragma unroll
            for (int q = 0; q < 8; q++) {
                ulonglong2 w = sW2[(i0 + 1) * 8 + q];
                acc2[(q << 1)]     = fma2(py, w.x, acc2[(q << 1)]);
                acc2[(q << 1) + 1] = fma2(py, w.y, acc2[(q << 1) + 1]);
            }
        }
    }

    // NOTE: acc2 pair layout — sW2 row r holds 8 ulonglong2 covering 32 outputs
    // in order: u2[q] = outputs {4q..4q+3} as two ull pairs. acc2 index mapping:
    // acc2[2q] = outs {4q,4q+1}, acc2[2q+1] = outs {4q+2,4q+3}. Consistent above.

    // ---- layer 3: 32 -> 3 ----
    float d0 = sB3[0], d1 = sB3[1], d2 = sB3[2];
#pragma unroll
    for (int j = 0; j < 16; j++) {
        float hx, hy; unpack2(acc2[j], hx, hy);
        hx = fmaxf(hx, 0.f); hy = fmaxf(hy, 0.f);
        int k0 = (j >> 1) * 4 + (j & 1) * 2;  // output index of hx
        d0 = fmaf(hx, sW3[3 * k0 + 0], d0);
        d1 = fmaf(hx, sW3[3 * k0 + 1], d1);
        d2 = fmaf(hx, sW3[3 * k0 + 2], d2);
        d0 = fmaf(hy, sW3[3 * (k0 + 1) + 0], d0);
        d1 = fmaf(hy, sW3[3 * (k0 + 1) + 1], d1);
        d2 = fmaf(hy, sW3[3 * (k0 + 1) + 2], d2);
    }

    o12[t] = ft12 - d0;
    o13[t] = ft13 - d1;
    o23[t] = ft23 - d2;
    atomicAdd(out_edge + a, d0);
    atomicAdd(out_edge + b, d1);
    atomicAdd(out_edge + c, d2);
}

// ---------------- launcher ----------------------------------------------------
extern "C" void kernel_launch(void* const* d_in, const int* in_sizes, int n_in,
                              void* d_out, int out_size) {
    const float* edge_costs = (const float*)d_in[0];
    const float* t12 = (const float*)d_in[1];
    const float* t13 = (const float*)d_in[2];
    const float* t23 = (const float*)d_in[3];
    const int*   c12 = (const int*)d_in[4];
    const int*   c13 = (const int*)d_in[5];
    const int*   c23 = (const int*)d_in[6];
    // d_in[7] edge_counter unused
    const int*   eidx = (const int*)d_in[8];
    // d_in[9] num_nodes (device scalar; compile-time N_NODES used)
    const float* W1  = (const float*)d_in[10];
    const float* b1  = (const float*)d_in[11];
    const float* W2  = (const float*)d_in[12];
    const float* b2  = (const float*)d_in[13];
    const float* Wm1 = (const float*)d_in[14];
    const float* bm1 = (const float*)d_in[15];
    const float* Wm2 = (const float*)d_in[16];
    const float* bm2 = (const float*)d_in[17];
    const float* Wm3 = (const float*)d_in[18];
    const float* bm3 = (const float*)d_in[19];

    int E = in_sizes[0];       // 200000
    int T = in_sizes[1];       // 2000000
    const int* src = eidx;
    const int* dst = eidx + E;

    float* out_edge = (float*)d_out;
    float* o12 = out_edge + E;
    float* o13 = o12 + T;
    float* o23 = o13 + T;

    const int B = 256;
    k_init <<<(N_NODES * HID + B - 1) / B, B>>>(edge_costs, out_edge, E);
    k_deg  <<<(E + B - 1) / B, B>>>(dst, E);
    k_dinv <<<(N_NODES + B - 1) / B, B>>>();
    k_acc1 <<<(E + B - 1) / B, B>>>(src, dst, E);
    k_node1<<<(N_NODES + B - 1) / B, B>>>(W1, b1, W2);
    k_msg  <<<((size_t)E * 32 + B - 1) / B, B>>>(src, dst, E);
    k_node2<<<(N_NODES * HID + B - 1) / B, B>>>(b2);
    k_tri  <<<(T + 255) / 256, 256>>>(t12, t13, t23, c12, c13, c23, edge_costs,
                                      Wm1, bm1, Wm2, bm2, Wm3, bm3,
                                      out_edge, o12, o13, o23, T);
}

// round 3
// speedup vs baseline: 1.5674x; 1.5500x over previous
#include <cuda_runtime.h>
#include <cstdint>

#define N_NODES 200000
#define HID 32

// ---------------- scratch (static device globals; no allocation) ----------
__device__ int   g_deg[N_NODES];
__device__ float g_dinv[N_NODES];
__device__ float g_acc1[N_NODES];
__device__ float g_h2 [N_NODES * HID];
__device__ float g_acc2[N_NODES * HID];
__device__ float g_x2 [N_NODES * HID];

// ---------------- GCN stages (unchanged; ~100us total) ---------------------
__global__ void k_init(const float* __restrict__ ec, float* __restrict__ out_edge, int E) {
    int i = blockIdx.x * blockDim.x + threadIdx.x;
    if (i < N_NODES * HID) g_acc2[i] = 0.f;
    if (i < N_NODES) { g_deg[i] = 0; g_acc1[i] = 0.f; }
    if (i < E) out_edge[i] = ec[i];
}
__global__ void k_deg(const int* __restrict__ dst, int E) {
    int e = blockIdx.x * blockDim.x + threadIdx.x;
    if (e < E) atomicAdd(&g_deg[dst[e]], 1);
}
__global__ void k_dinv() {
    int n = blockIdx.x * blockDim.x + threadIdx.x;
    if (n < N_NODES) g_dinv[n] = rsqrtf((float)(g_deg[n] + 1));
}
__global__ void k_acc1(const int* __restrict__ src, const int* __restrict__ dst, int E) {
    int e = blockIdx.x * blockDim.x + threadIdx.x;
    if (e < E) atomicAdd(&g_acc1[dst[e]], g_dinv[src[e]]);
}
__global__ void k_node1(const float* __restrict__ W1, const float* __restrict__ b1,
                        const float* __restrict__ W2) {
    __shared__ float sW1[HID], sB1[HID], sW2[HID * HID];
    for (int i = threadIdx.x; i < HID; i += blockDim.x) { sW1[i] = W1[i]; sB1[i] = b1[i]; }
    for (int i = threadIdx.x; i < HID * HID; i += blockDim.x) sW2[i] = W2[i];
    __syncthreads();
    int n = blockIdx.x * blockDim.x + threadIdx.x;
    if (n >= N_NODES) return;
    float dv = g_dinv[n];
    float s1 = dv * (g_acc1[n] + dv);
    float x1[HID];
#pragma unroll
    for (int k = 0; k < HID; k++) x1[k] = fmaxf(fmaf(sW1[k], s1, sB1[k]), 0.f);
    float h2[HID];
#pragma unroll
    for (int j = 0; j < HID; j++) h2[j] = 0.f;
#pragma unroll
    for (int i = 0; i < HID; i++) {
        float xi = x1[i];
#pragma unroll
        for (int j = 0; j < HID; j++) h2[j] = fmaf(xi, sW2[i * HID + j], h2[j]);
    }
    float4* o = (float4*)(g_h2 + (size_t)n * HID);
#pragma unroll
    for (int q = 0; q < 8; q++)
        o[q] = make_float4(h2[4 * q], h2[4 * q + 1], h2[4 * q + 2], h2[4 * q + 3]);
}
__global__ void k_msg(const int* __restrict__ src, const int* __restrict__ dst, int E) {
    int idx = blockIdx.x * blockDim.x + threadIdx.x;
    int e = idx >> 5, k = idx & 31;
    if (e >= E) return;
    int s = src[e], d = dst[e];
    float nrm = g_dinv[s] * g_dinv[d];
    atomicAdd(&g_acc2[(size_t)d * HID + k], g_h2[(size_t)s * HID + k] * nrm);
}
__global__ void k_node2(const float* __restrict__ b2) {
    int i = blockIdx.x * blockDim.x + threadIdx.x;
    if (i >= N_NODES * HID) return;
    int n = i >> 5, k = i & 31;
    float dv = g_dinv[n];
    g_x2[i] = fmaxf(g_acc2[i] + g_h2[i] * dv * dv + b2[k], 0.f);
}

// ---------------- stage 7: triangle MLP on tensor cores (tf32 HMMA) --------
#define WPB 8          // warps per block
#define TILE 16        // triangles per warp-tile

// shared layout (floats). strides chosen conflict-free for fragment access.
#define SW1_STRIDE 72  // [40][72] tf32 bits
#define SW2_STRIDE 40  // [64][40] tf32 bits
#define SA_STRIDE  44  // [16][44] inputs f32 (cols 0..39 used)
#define SH_STRIDE  68  // [16][68] h1 f32 (cols 0..63 used)
#define OFF_W1 0
#define OFF_W2 (OFF_W1 + 40 * SW1_STRIDE)          // 2880
#define OFF_B1 (OFF_W2 + 64 * SW2_STRIDE)          // 5440
#define OFF_B2 (OFF_B1 + 64)
#define OFF_W3 (OFF_B2 + 32)
#define OFF_B3 (OFF_W3 + 96)
#define OFF_WARP (OFF_B3 + 8)                      // 5640 (16B aligned)
#define WARP_FLOATS (TILE * SA_STRIDE + TILE * SH_STRIDE)  // 704 + 1088 = 1792
#define SMEM_FLOATS (OFF_WARP + WPB * WARP_FLOATS)         // 19976
#define SMEM_BYTES  (SMEM_FLOATS * 4)                      // 79904

__device__ __forceinline__ uint32_t f2tf(float x) {
    uint32_t r; asm("cvt.rna.tf32.f32 %0,%1;" : "=r"(r) : "f"(x)); return r;
}
__device__ __forceinline__ void mma_tf32(
    float& c0, float& c1, float& c2, float& c3,
    uint32_t a0, uint32_t a1, uint32_t a2, uint32_t a3,
    uint32_t b0, uint32_t b1)
{
    asm volatile(
        "mma.sync.aligned.m16n8k8.row.col.f32.tf32.tf32.f32 "
        "{%0,%1,%2,%3},{%4,%5,%6,%7},{%8,%9},{%0,%1,%2,%3};"
        : "+f"(c0), "+f"(c1), "+f"(c2), "+f"(c3)
        : "r"(a0), "r"(a1), "r"(a2), "r"(a3), "r"(b0), "r"(b1));
}

__global__ void __launch_bounds__(WPB * 32) k_tri(
    const float* __restrict__ t12, const float* __restrict__ t13, const float* __restrict__ t23,
    const int* __restrict__ c12, const int* __restrict__ c13, const int* __restrict__ c23,
    const float* __restrict__ ec,
    const float* __restrict__ Wm1, const float* __restrict__ bm1,
    const float* __restrict__ Wm2, const float* __restrict__ bm2,
    const float* __restrict__ Wm3, const float* __restrict__ bm3,
    float* __restrict__ out_edge,
    float* __restrict__ o12, float* __restrict__ o13, float* __restrict__ o23, int T)
{
    extern __shared__ float smem[];
    uint32_t* sW1 = (uint32_t*)(smem + OFF_W1);
    uint32_t* sW2 = (uint32_t*)(smem + OFF_W2);
    float* sB1 = smem + OFF_B1;
    float* sB2 = smem + OFF_B2;
    float* sW3 = smem + OFF_W3;
    float* sB3 = smem + OFF_B3;

    const int tid = threadIdx.x;
    // ---- load weights to shared (tf32 bits, 1/3 folded into W1 rows 3..34)
    for (int i = tid; i < 40 * SW1_STRIDE; i += blockDim.x) {
        int row = i / SW1_STRIDE, col = i % SW1_STRIDE;
        float v = 0.f;
        if (row < 38 && col < 64) {
            v = Wm1[row * 64 + col];
            if (row >= 3 && row < 35) v *= (1.f / 3.f);
        }
        sW1[i] = f2tf(v);
    }
    for (int i = tid; i < 64 * SW2_STRIDE; i += blockDim.x) {
        int row = i / SW2_STRIDE, col = i % SW2_STRIDE;
        float v = (col < 32) ? Wm2[row * 32 + col] : 0.f;
        sW2[i] = f2tf(v);
    }
    if (tid < 64) sB1[tid] = bm1[tid];
    if (tid < 32) sB2[tid] = bm2[tid];
    for (int i = tid; i < 96; i += blockDim.x) sW3[i] = Wm3[i];
    if (tid < 3) sB3[tid] = bm3[tid];
    __syncthreads();

    const int wid  = tid >> 5;
    const int lane = tid & 31;
    const int grp  = lane >> 2;   // 0..7  (A row group / B col group)
    const int qd   = lane & 3;    // 0..3  (A col / B row)
    float* sA = smem + OFF_WARP + wid * WARP_FLOATS;          // [16][44]
    float* sH = sA + TILE * SA_STRIDE;                        // [16][68]

    const int ntiles = (T + TILE - 1) / TILE;
    const int gw = blockIdx.x * WPB + wid;
    const int gstride = gridDim.x * WPB;

    for (int tile = gw; tile < ntiles; tile += gstride) {
        const int t0 = tile * TILE;

        // ---- gather phase -------------------------------------------------
        int ia = 0, ib = 0, icx = 0;
        float f12 = 0.f, f13 = 0.f, f23 = 0.f;
        if (lane < TILE) {
            int t = t0 + lane;
            if (t < T) {
                ia = c12[t]; ib = c13[t]; icx = c23[t];
                f12 = t12[t]; f13 = t13[t]; f23 = t23[t];
            }
            float ea = 0.f, eb = 0.f, ecv = 0.f;
            if (t0 + lane < T) { ea = ec[ia]; eb = ec[ib]; ecv = ec[icx]; }
            float* row = sA + lane * SA_STRIDE;
            row[0] = f12; row[1] = f13; row[2] = f23;
            row[35] = ea; row[36] = eb; row[37] = ecv;
            row[38] = 0.f; row[39] = 0.f;
        }
        __syncwarp();
#pragma unroll 4
        for (int rr = 0; rr < TILE; rr++) {
            int ja = __shfl_sync(0xffffffffu, ia, rr);
            int jb = __shfl_sync(0xffffffffu, ib, rr);
            int jc = __shfl_sync(0xffffffffu, icx, rr);
            float v = 0.f;
            if (t0 + rr < T)
                v = g_x2[(size_t)ja * HID + lane] + g_x2[(size_t)jb * HID + lane]
                  + g_x2[(size_t)jc * HID + lane];
            sA[rr * SA_STRIDE + 3 + lane] = v;   // 1/3 folded in sW1
        }
        __syncwarp();

        // ---- layer 1: [16x40] @ [40x64] -----------------------------------
        uint32_t A0[5], A1[5], A2[5], A3[5];
#pragma unroll
        for (int kt = 0; kt < 5; kt++) {
            A0[kt] = f2tf(sA[grp * SA_STRIDE + kt * 8 + qd]);
            A1[kt] = f2tf(sA[(grp + 8) * SA_STRIDE + kt * 8 + qd]);
            A2[kt] = f2tf(sA[grp * SA_STRIDE + kt * 8 + qd + 4]);
            A3[kt] = f2tf(sA[(grp + 8) * SA_STRIDE + kt * 8 + qd + 4]);
        }
#pragma unroll
        for (int nt = 0; nt < 8; nt++) {
            int colc = nt * 8 + 2 * qd;
            float c0 = sB1[colc], c1 = sB1[colc + 1];
            float c2 = c0, c3 = c1;
#pragma unroll
            for (int kt = 0; kt < 5; kt++) {
                uint32_t b0 = sW1[(kt * 8 + qd) * SW1_STRIDE + nt * 8 + grp];
                uint32_t b1 = sW1[(kt * 8 + qd + 4) * SW1_STRIDE + nt * 8 + grp];
                mma_tf32(c0, c1, c2, c3, A0[kt], A1[kt], A2[kt], A3[kt], b0, b1);
            }
            sH[grp * SH_STRIDE + colc]           = fmaxf(c0, 0.f);
            sH[grp * SH_STRIDE + colc + 1]       = fmaxf(c1, 0.f);
            sH[(grp + 8) * SH_STRIDE + colc]     = fmaxf(c2, 0.f);
            sH[(grp + 8) * SH_STRIDE + colc + 1] = fmaxf(c3, 0.f);
        }
        __syncwarp();

        // ---- layer 2: [16x64] @ [64x32] -----------------------------------
        uint32_t H0[8], H1[8], H2[8], H3[8];
#pragma unroll
        for (int kt = 0; kt < 8; kt++) {
            H0[kt] = f2tf(sH[grp * SH_STRIDE + kt * 8 + qd]);
            H1[kt] = f2tf(sH[(grp + 8) * SH_STRIDE + kt * 8 + qd]);
            H2[kt] = f2tf(sH[grp * SH_STRIDE + kt * 8 + qd + 4]);
            H3[kt] = f2tf(sH[(grp + 8) * SH_STRIDE + kt * 8 + qd + 4]);
        }
#pragma unroll
        for (int nt = 0; nt < 4; nt++) {
            int colc = nt * 8 + 2 * qd;
            float c0 = sB2[colc], c1 = sB2[colc + 1];
            float c2 = c0, c3 = c1;
#pragma unroll
            for (int kt = 0; kt < 8; kt++) {
                uint32_t b0 = sW2[(kt * 8 + qd) * SW2_STRIDE + nt * 8 + grp];
                uint32_t b1 = sW2[(kt * 8 + qd + 4) * SW2_STRIDE + nt * 8 + grp];
                mma_tf32(c0, c1, c2, c3, H0[kt], H1[kt], H2[kt], H3[kt], b0, b1);
            }
            // store relu(h2) into sA region (reused as [16][44] h2 staging)
            sA[grp * SA_STRIDE + colc]           = fmaxf(c0, 0.f);
            sA[grp * SA_STRIDE + colc + 1]       = fmaxf(c1, 0.f);
            sA[(grp + 8) * SA_STRIDE + colc]     = fmaxf(c2, 0.f);
            sA[(grp + 8) * SA_STRIDE + colc + 1] = fmaxf(c3, 0.f);
        }
        __syncwarp();

        // ---- layer 3 (scalar fp32) + epilogue -----------------------------
        if (lane < TILE && (t0 + lane) < T) {
            const float* h2 = sA + lane * SA_STRIDE;
            float d0 = sB3[0], d1 = sB3[1], d2 = sB3[2];
#pragma unroll
            for (int k = 0; k < 32; k++) {
                float h = h2[k];
                d0 = fmaf(h, sW3[3 * k + 0], d0);
                d1 = fmaf(h, sW3[3 * k + 1], d1);
                d2 = fmaf(h, sW3[3 * k + 2], d2);
            }
            int t = t0 + lane;
            o12[t] = f12 - d0;
            o13[t] = f13 - d1;
            o23[t] = f23 - d2;
            atomicAdd(out_edge + ia,  d0);
            atomicAdd(out_edge + ib,  d1);
            atomicAdd(out_edge + icx, d2);
        }
        __syncwarp();
    }
}

// ---------------- launcher ----------------------------------------------------
extern "C" void kernel_launch(void* const* d_in, const int* in_sizes, int n_in,
                              void* d_out, int out_size) {
    const float* edge_costs = (const float*)d_in[0];
    const float* t12 = (const float*)d_in[1];
    const float* t13 = (const float*)d_in[2];
    const float* t23 = (const float*)d_in[3];
    const int*   c12 = (const int*)d_in[4];
    const int*   c13 = (const int*)d_in[5];
    const int*   c23 = (const int*)d_in[6];
    const int*   eidx = (const int*)d_in[8];
    const float* W1  = (const float*)d_in[10];
    const float* b1  = (const float*)d_in[11];
    const float* W2  = (const float*)d_in[12];
    const float* b2  = (const float*)d_in[13];
    const float* Wm1 = (const float*)d_in[14];
    const float* bm1 = (const float*)d_in[15];
    const float* Wm2 = (const float*)d_in[16];
    const float* bm2 = (const float*)d_in[17];
    const float* Wm3 = (const float*)d_in[18];
    const float* bm3 = (const float*)d_in[19];

    int E = in_sizes[0];       // 200000
    int T = in_sizes[1];       // 2000000
    const int* src = eidx;
    const int* dst = eidx + E;

    float* out_edge = (float*)d_out;
    float* o12 = out_edge + E;
    float* o13 = o12 + T;
    float* o23 = o13 + T;

    const int B = 256;
    k_init <<<(N_NODES * HID + B - 1) / B, B>>>(edge_costs, out_edge, E);
    k_deg  <<<(E + B - 1) / B, B>>>(dst, E);
    k_dinv <<<(N_NODES + B - 1) / B, B>>>();
    k_acc1 <<<(E + B - 1) / B, B>>>(src, dst, E);
    k_node1<<<(N_NODES + B - 1) / B, B>>>(W1, b1, W2);
    k_msg  <<<((size_t)E * 32 + B - 1) / B, B>>>(src, dst, E);
    k_node2<<<(N_NODES * HID + B - 1) / B, B>>>(b2);

    static int smem_set = 0;
    if (!smem_set) {
        cudaFuncSetAttribute(k_tri, cudaFuncAttributeMaxDynamicSharedMemorySize, SMEM_BYTES);
        smem_set = 1;
    }
    k_tri<<<1184, WPB * 32, SMEM_BYTES>>>(t12, t13, t23, c12, c13, c23, edge_costs,
                                          Wm1, bm1, Wm2, bm2, Wm3, bm3,
                                          out_edge, o12, o13, o23, T);
}

// round 4
// speedup vs baseline: 2.1011x; 1.3405x over previous
#include <cuda_runtime.h>
#include <cstdint>

#define N_NODES 200000
#define HID 32

// ---------------- scratch (static device globals; no allocation) ----------
__device__ int   g_deg[N_NODES];
__device__ float g_dinv[N_NODES];
__device__ float g_acc1[N_NODES];
__device__ float g_h2 [N_NODES * HID];
__device__ float g_acc2[N_NODES * HID];
__device__ float g_x2 [N_NODES * HID];

// ---------------- GCN stages ------------------------------------------------
__global__ void k_init(const float* __restrict__ ec, float* __restrict__ out_edge, int E) {
    int i = blockIdx.x * blockDim.x + threadIdx.x;
    if (i < N_NODES * HID) g_acc2[i] = 0.f;
    if (i < N_NODES) { g_deg[i] = 0; g_acc1[i] = 0.f; }
    if (i < E) out_edge[i] = ec[i];
}
__global__ void k_deg(const int* __restrict__ dst, int E) {
    int e = blockIdx.x * blockDim.x + threadIdx.x;
    if (e < E) atomicAdd(&g_deg[dst[e]], 1);
}
__global__ void k_dinv() {
    int n = blockIdx.x * blockDim.x + threadIdx.x;
    if (n < N_NODES) g_dinv[n] = rsqrtf((float)(g_deg[n] + 1));
}
__global__ void k_acc1(const int* __restrict__ src, const int* __restrict__ dst, int E) {
    int e = blockIdx.x * blockDim.x + threadIdx.x;
    if (e < E) atomicAdd(&g_acc1[dst[e]], g_dinv[src[e]]);
}
__global__ void k_node1(const float* __restrict__ W1, const float* __restrict__ b1,
                        const float* __restrict__ W2) {
    __shared__ float sW1[HID], sB1[HID], sW2[HID * HID];
    for (int i = threadIdx.x; i < HID; i += blockDim.x) { sW1[i] = W1[i]; sB1[i] = b1[i]; }
    for (int i = threadIdx.x; i < HID * HID; i += blockDim.x) sW2[i] = W2[i];
    __syncthreads();
    int n = blockIdx.x * blockDim.x + threadIdx.x;
    if (n >= N_NODES) return;
    float dv = g_dinv[n];
    float s1 = dv * (g_acc1[n] + dv);
    float x1[HID];
#pragma unroll
    for (int k = 0; k < HID; k++) x1[k] = fmaxf(fmaf(sW1[k], s1, sB1[k]), 0.f);
    float h2[HID];
#pragma unroll
    for (int j = 0; j < HID; j++) h2[j] = 0.f;
#pragma unroll
    for (int i = 0; i < HID; i++) {
        float xi = x1[i];
#pragma unroll
        for (int j = 0; j < HID; j++) h2[j] = fmaf(xi, sW2[i * HID + j], h2[j]);
    }
    float4* o = (float4*)(g_h2 + (size_t)n * HID);
#pragma unroll
    for (int q = 0; q < 8; q++)
        o[q] = make_float4(h2[4 * q], h2[4 * q + 1], h2[4 * q + 2], h2[4 * q + 3]);
}
__global__ void k_msg(const int* __restrict__ src, const int* __restrict__ dst, int E) {
    int idx = blockIdx.x * blockDim.x + threadIdx.x;
    int e = idx >> 5, k = idx & 31;
    if (e >= E) return;
    int s = src[e], d = dst[e];
    float nrm = g_dinv[s] * g_dinv[d];
    atomicAdd(&g_acc2[(size_t)d * HID + k], g_h2[(size_t)s * HID + k] * nrm);
}
__global__ void k_node2(const float* __restrict__ b2) {
    int i = blockIdx.x * blockDim.x + threadIdx.x;
    if (i >= N_NODES * HID) return;
    int n = i >> 5, k = i & 31;
    float dv = g_dinv[n];
    g_x2[i] = fmaxf(g_acc2[i] + g_h2[i] * dv * dv + b2[k], 0.f);
}

// ---------------- stage 7: triangle MLP on tensor cores ---------------------
#define WPB  4
#define TILE 16
#define SW1S 72
#define SW2S 40
#define SW3S 40
#define SAS  44
#define SHS  68
#define OFF_W1  0
#define OFF_W2  (40 * SW1S)                 // 2880
#define OFF_W3B (OFF_W2 + 64 * SW2S)        // 5440
#define OFF_B1  (OFF_W3B + 32 * SW3S)       // 6720
#define OFF_B2  (OFF_B1 + 64)               // 6784
#define OFF_B3  (OFF_B2 + 32)               // 6816
#define OFF_WARP 6824                        // 16B-aligned in bytes
#define WARP_FLOATS (TILE * SAS + TILE * SHS)       // 1792
#define SMEM_FLOATS (OFF_WARP + WPB * WARP_FLOATS)  // 13992
#define SMEM_BYTES  (SMEM_FLOATS * 4)               // 55968

__device__ __forceinline__ uint32_t f2tf(float x) {
    uint32_t r; asm("cvt.rna.tf32.f32 %0,%1;" : "=r"(r) : "f"(x)); return r;
}
__device__ __forceinline__ void mma_tf32(
    float& c0, float& c1, float& c2, float& c3,
    uint32_t a0, uint32_t a1, uint32_t a2, uint32_t a3,
    uint32_t b0, uint32_t b1)
{
    asm volatile(
        "mma.sync.aligned.m16n8k8.row.col.f32.tf32.tf32.f32 "
        "{%0,%1,%2,%3},{%4,%5,%6,%7},{%8,%9},{%0,%1,%2,%3};"
        : "+f"(c0), "+f"(c1), "+f"(c2), "+f"(c3)
        : "r"(a0), "r"(a1), "r"(a2), "r"(a3), "r"(b0), "r"(b1));
}

__global__ void __launch_bounds__(WPB * 32) k_tri(
    const float* __restrict__ t12, const float* __restrict__ t13, const float* __restrict__ t23,
    const int* __restrict__ c12, const int* __restrict__ c13, const int* __restrict__ c23,
    const float* __restrict__ ec,
    const float* __restrict__ Wm1, const float* __restrict__ bm1,
    const float* __restrict__ Wm2, const float* __restrict__ bm2,
    const float* __restrict__ Wm3, const float* __restrict__ bm3,
    float* __restrict__ out_edge,
    float* __restrict__ o12, float* __restrict__ o13, float* __restrict__ o23, int T)
{
    extern __shared__ float smem[];
    uint32_t* sW1  = (uint32_t*)(smem + OFF_W1);
    uint32_t* sW2  = (uint32_t*)(smem + OFF_W2);
    uint32_t* sW3b = (uint32_t*)(smem + OFF_W3B);
    float* sB1 = smem + OFF_B1;
    float* sB2 = smem + OFF_B2;
    float* sB3 = smem + OFF_B3;

    const int tid = threadIdx.x;
    // ---- weights to shared (tf32 bits; 1/3 folded into W1 rows 3..34) ----
    for (int i = tid; i < 40 * SW1S; i += blockDim.x) {
        int row = i / SW1S, col = i % SW1S;
        float v = 0.f;
        if (row < 38 && col < 64) {
            v = Wm1[row * 64 + col];
            if (row >= 3 && row < 35) v *= (1.f / 3.f);
        }
        sW1[i] = f2tf(v);
    }
    for (int i = tid; i < 64 * SW2S; i += blockDim.x) {
        int row = i / SW2S, col = i % SW2S;
        sW2[i] = f2tf((col < 32) ? Wm2[row * 32 + col] : 0.f);
    }
    for (int i = tid; i < 32 * SW3S; i += blockDim.x) {
        int row = i / SW3S, col = i % SW3S;
        sW3b[i] = f2tf((col < 3) ? Wm3[row * 3 + col] : 0.f);
    }
    if (tid < 64) sB1[tid] = bm1[tid];
    if (tid < 32) sB2[tid] = bm2[tid];
    if (tid < 3)  sB3[tid] = bm3[tid];
    __syncthreads();

    const int wid  = tid >> 5;
    const int lane = tid & 31;
    const int grp  = lane >> 2;   // 0..7
    const int qd   = lane & 3;    // 0..3
    float* sA = smem + OFF_WARP + wid * WARP_FLOATS;   // [16][44]
    float* sH = sA + TILE * SAS;                       // [16][68]

    // ---- persistent register fragments (loop-invariant weights) ----
    uint32_t w2r[8][4][2];
#pragma unroll
    for (int kt = 0; kt < 8; kt++)
#pragma unroll
        for (int nt = 0; nt < 4; nt++) {
            w2r[kt][nt][0] = sW2[(kt * 8 + qd)     * SW2S + nt * 8 + grp];
            w2r[kt][nt][1] = sW2[(kt * 8 + qd + 4) * SW2S + nt * 8 + grp];
        }
    uint32_t w3r[4][2];
#pragma unroll
    for (int kt = 0; kt < 4; kt++) {
        w3r[kt][0] = sW3b[(kt * 8 + qd)     * SW3S + grp];
        w3r[kt][1] = sW3b[(kt * 8 + qd + 4) * SW3S + grp];
    }
    const float b3c0 = (2 * qd     < 3) ? sB3[2 * qd]     : 0.f;
    const float b3c1 = (2 * qd + 1 < 3) ? sB3[2 * qd + 1] : 0.f;

    const int ntiles = (T + TILE - 1) / TILE;
    const int gw = blockIdx.x * WPB + wid;
    const int gstride = gridDim.x * WPB;

    for (int tile = gw; tile < ntiles; tile += gstride) {
        const int t0 = tile * TILE;

        // ---- gather phase ------------------------------------------------
        int ia = 0, ib = 0, icx = 0;
        float f12 = 0.f, f13 = 0.f, f23 = 0.f;
        if (lane < TILE) {
            int t = t0 + lane;
            float ea = 0.f, eb = 0.f, ecv = 0.f;
            if (t < T) {
                ia = c12[t]; ib = c13[t]; icx = c23[t];
                f12 = t12[t]; f13 = t13[t]; f23 = t23[t];
                ea = ec[ia]; eb = ec[ib]; ecv = ec[icx];
            }
            int* sIdx = (int*)sH;
            sIdx[lane] = ia; sIdx[16 + lane] = ib; sIdx[32 + lane] = icx;
            float* row = sA + lane * SAS;
            row[0] = f12; row[1] = f13; row[2] = f23;
            row[35] = ea; row[36] = eb; row[37] = ecv;
            row[38] = 0.f; row[39] = 0.f;
        }
        __syncwarp();
        {
            const int* sIdx = (const int*)sH;
#pragma unroll
            for (int half = 0; half < 2; half++) {
                const int base = half * 8;
                float va[8], vb[8], vc[8];
#pragma unroll
                for (int r = 0; r < 8; r++) va[r] = g_x2[(size_t)sIdx[base + r] * HID + lane];
#pragma unroll
                for (int r = 0; r < 8; r++) vb[r] = g_x2[(size_t)sIdx[16 + base + r] * HID + lane];
#pragma unroll
                for (int r = 0; r < 8; r++) vc[r] = g_x2[(size_t)sIdx[32 + base + r] * HID + lane];
#pragma unroll
                for (int r = 0; r < 8; r++)
                    sA[(base + r) * SAS + 3 + lane] = va[r] + vb[r] + vc[r];  // 1/3 in sW1
            }
        }
        __syncwarp();

        // ---- layer 1: [16x40] @ [40x64] (kt-outer, 8 independent accs) ---
        float a1[8][4];
#pragma unroll
        for (int nt = 0; nt < 8; nt++) {
            float2 bb = *(const float2*)(sB1 + nt * 8 + 2 * qd);
            a1[nt][0] = bb.x; a1[nt][1] = bb.y; a1[nt][2] = bb.x; a1[nt][3] = bb.y;
        }
#pragma unroll
        for (int kt = 0; kt < 5; kt++) {
            uint32_t A0 = f2tf(sA[grp * SAS + kt * 8 + qd]);
            uint32_t A1 = f2tf(sA[(grp + 8) * SAS + kt * 8 + qd]);
            uint32_t A2 = f2tf(sA[grp * SAS + kt * 8 + qd + 4]);
            uint32_t A3 = f2tf(sA[(grp + 8) * SAS + kt * 8 + qd + 4]);
#pragma unroll
            for (int nt = 0; nt < 8; nt++) {
                uint32_t b0 = sW1[(kt * 8 + qd)     * SW1S + nt * 8 + grp];
                uint32_t b1 = sW1[(kt * 8 + qd + 4) * SW1S + nt * 8 + grp];
                mma_tf32(a1[nt][0], a1[nt][1], a1[nt][2], a1[nt][3], A0, A1, A2, A3, b0, b1);
            }
        }
#pragma unroll
        for (int nt = 0; nt < 8; nt++) {
            int colc = nt * 8 + 2 * qd;
            sH[grp * SHS + colc]           = fmaxf(a1[nt][0], 0.f);
            sH[grp * SHS + colc + 1]       = fmaxf(a1[nt][1], 0.f);
            sH[(grp + 8) * SHS + colc]     = fmaxf(a1[nt][2], 0.f);
            sH[(grp + 8) * SHS + colc + 1] = fmaxf(a1[nt][3], 0.f);
        }
        __syncwarp();

        // ---- layer 2: [16x64] @ [64x32] (W2 in registers) ----------------
        float a2[4][4];
#pragma unroll
        for (int nt = 0; nt < 4; nt++) {
            float2 bb = *(const float2*)(sB2 + nt * 8 + 2 * qd);
            a2[nt][0] = bb.x; a2[nt][1] = bb.y; a2[nt][2] = bb.x; a2[nt][3] = bb.y;
        }
#pragma unroll
        for (int kt = 0; kt < 8; kt++) {
            uint32_t H0 = f2tf(sH[grp * SHS + kt * 8 + qd]);
            uint32_t H1 = f2tf(sH[(grp + 8) * SHS + kt * 8 + qd]);
            uint32_t H2 = f2tf(sH[grp * SHS + kt * 8 + qd + 4]);
            uint32_t H3 = f2tf(sH[(grp + 8) * SHS + kt * 8 + qd + 4]);
#pragma unroll
            for (int nt = 0; nt < 4; nt++)
                mma_tf32(a2[nt][0], a2[nt][1], a2[nt][2], a2[nt][3],
                         H0, H1, H2, H3, w2r[kt][nt][0], w2r[kt][nt][1]);
        }
#pragma unroll
        for (int nt = 0; nt < 4; nt++) {
            int colc = nt * 8 + 2 * qd;
            sA[grp * SAS + colc]           = fmaxf(a2[nt][0], 0.f);
            sA[grp * SAS + colc + 1]       = fmaxf(a2[nt][1], 0.f);
            sA[(grp + 8) * SAS + colc]     = fmaxf(a2[nt][2], 0.f);
            sA[(grp + 8) * SAS + colc + 1] = fmaxf(a2[nt][3], 0.f);
        }
        __syncwarp();

        // ---- layer 3: [16x32] @ [32x8(3)] via MMA (W3 in registers) ------
        float d0 = b3c0, d1 = b3c1, d2 = b3c0, d3 = b3c1;
#pragma unroll
        for (int kt = 0; kt < 4; kt++) {
            uint32_t A0 = f2tf(sA[grp * SAS + kt * 8 + qd]);
            uint32_t A1 = f2tf(sA[(grp + 8) * SAS + kt * 8 + qd]);
            uint32_t A2 = f2tf(sA[grp * SAS + kt * 8 + qd + 4]);
            uint32_t A3 = f2tf(sA[(grp + 8) * SAS + kt * 8 + qd + 4]);
            mma_tf32(d0, d1, d2, d3, A0, A1, A2, A3, w3r[kt][0], w3r[kt][1]);
        }
        float* sD = sH;   // reuse as [16][4]
        if (2 * qd < 3)     { sD[grp * 4 + 2 * qd]       = d0; sD[(grp + 8) * 4 + 2 * qd]     = d2; }
        if (2 * qd + 1 < 3) { sD[grp * 4 + 2 * qd + 1]   = d1; sD[(grp + 8) * 4 + 2 * qd + 1] = d3; }
        __syncwarp();

        // ---- epilogue ----------------------------------------------------
        if (lane < TILE && (t0 + lane) < T) {
            float4 dd = *(const float4*)(sD + lane * 4);
            int t = t0 + lane;
            o12[t] = f12 - dd.x;
            o13[t] = f13 - dd.y;
            o23[t] = f23 - dd.z;
            atomicAdd(out_edge + ia,  dd.x);
            atomicAdd(out_edge + ib,  dd.y);
            atomicAdd(out_edge + icx, dd.z);
        }
        __syncwarp();
    }
}

// ---------------- launcher ----------------------------------------------------
extern "C" void kernel_launch(void* const* d_in, const int* in_sizes, int n_in,
                              void* d_out, int out_size) {
    const float* edge_costs = (const float*)d_in[0];
    const float* t12 = (const float*)d_in[1];
    const float* t13 = (const float*)d_in[2];
    const float* t23 = (const float*)d_in[3];
    const int*   c12 = (const int*)d_in[4];
    const int*   c13 = (const int*)d_in[5];
    const int*   c23 = (const int*)d_in[6];
    const int*   eidx = (const int*)d_in[8];
    const float* W1  = (const float*)d_in[10];
    const float* b1  = (const float*)d_in[11];
    const float* W2  = (const float*)d_in[12];
    const float* b2  = (const float*)d_in[13];
    const float* Wm1 = (const float*)d_in[14];
    const float* bm1 = (const float*)d_in[15];
    const float* Wm2 = (const float*)d_in[16];
    const float* bm2 = (const float*)d_in[17];
    const float* Wm3 = (const float*)d_in[18];
    const float* bm3 = (const float*)d_in[19];

    int E = in_sizes[0];       // 200000
    int T = in_sizes[1];       // 2000000
    const int* src = eidx;
    const int* dst = eidx + E;

    float* out_edge = (float*)d_out;
    float* o12 = out_edge + E;
    float* o13 = o12 + T;
    float* o23 = o13 + T;

    const int B = 256;
    k_init <<<(N_NODES * HID + B - 1) / B, B>>>(edge_costs, out_edge, E);
    k_deg  <<<(E + B - 1) / B, B>>>(dst, E);
    k_dinv <<<(N_NODES + B - 1) / B, B>>>();
    k_acc1 <<<(E + B - 1) / B, B>>>(src, dst, E);
    k_node1<<<(N_NODES + B - 1) / B, B>>>(W1, b1, W2);
    k_msg  <<<((size_t)E * 32 + B - 1) / B, B>>>(src, dst, E);
    k_node2<<<(N_NODES * HID + B - 1) / B, B>>>(b2);

    cudaFuncSetAttribute(k_tri, cudaFuncAttributeMaxDynamicSharedMemorySize, SMEM_BYTES);
    k_tri<<<2368, WPB * 32, SMEM_BYTES>>>(t12, t13, t23, c12, c13, c23, edge_costs,
                                          Wm1, bm1, Wm2, bm2, Wm3, bm3,
                                          out_edge, o12, o13, o23, T);
}